// round 8
// baseline (speedup 1.0000x reference)
#include <cuda_runtime.h>

// DynamicLIF persistent kernel for GB300 (sm_103a), round 8.
// = R7 (72.7us: race-free count->leader->gen barrier, immediate release,
//   redundant conflict-free MLP, transposed w1) + ONE change:
//   warp-granular L2 prefetch of x[t+1] -- exactly 1 prefetch.global.L2
//   instruction per thread per step (each lane covers one distinct 128B
//   line; 256 lines = the whole 32KB next tile). R3's prefetch failed at
//   4B granularity (2048 ops/block-step flooded the LSU); this is 8x
//   cheaper in instructions and pure-hint semantics. Issued after the
//   publish, so the DRAM pull of x[t+1] overlaps the store burst + barrier
//   + MLP window; next step's loads then hit L2.

#define NB 32          // batch
#define NT 8           // time steps
#define NC 128         // channels
#define HW_ 1024       // H*W
#define CR 32          // C / red
#define THREADS 256
#define RPB 8          // channel rows per block
#define BPB 16         // blocks per batch
#define NBLOCKS (NB * BPB)   // 512
#define PUBS (BPB * RPB)     // 128 count-releases per batch per step

__device__ float    g_sums[NB * NC];
__device__ unsigned g_count[NB];   // zero at launch; leader resets each round
__device__ unsigned g_gen[NB];     // monotonic across replays

__device__ __forceinline__ unsigned ld_acquire(const unsigned* p) {
    unsigned v;
    asm volatile("ld.acquire.gpu.global.u32 %0, [%1];" : "=r"(v) : "l"(p));
    return v;
}
__device__ __forceinline__ void red_release_add(unsigned* p, unsigned v) {
    asm volatile("red.release.gpu.global.add.u32 [%0], %1;" :: "l"(p), "r"(v));
}

__global__ void __launch_bounds__(THREADS, 4)
lif_kernel(const float* __restrict__ x,
           const float* __restrict__ w1,
           const float* __restrict__ b1,
           const float* __restrict__ w2,
           const float* __restrict__ b2,
           float* __restrict__ out)
{
    __shared__ float s_w1t[NC * CR];   // 16 KB, TRANSPOSED: [c][row]
    __shared__ float s_warp[8][RPB];
    __shared__ float s_mean[NC];
    __shared__ float s_tau;

    const int tid = threadIdx.x;
    const int blk = blockIdx.x;
    const int b   = blk >> 4;          // batch
    const int sub = blk & 15;          // sub-block within batch
    const bool leader = (sub == 0);
    const int lane = tid & 31;
    const int warp = tid >> 5;

    // Cache w1 transposed: s_w1t[c*CR + r] = w1[r*NC + c].
    #pragma unroll
    for (int i = 0; i < (CR * NC) / THREADS; i++) {
        int idx = i * THREADS + tid;   // linear over w1 (row-major r*NC+c)
        int r = idx >> 7;
        int c = idx & 127;
        s_w1t[c * CR + r] = w1[idx];
    }
    __syncthreads();

    // base_gen read precedes this block's first publish (program order), and
    // the leader cannot release gen until all 16 blocks publish -> race-free
    // across startup skew AND graph replays.
    unsigned base_gen = 0;
    if (tid == 0) base_gen = *(volatile unsigned*)&g_gen[b];

    float tau = 0.5f;                  // TAU0
    float4 mem[RPB];
    #pragma unroll
    for (int i = 0; i < RPB; i++) mem[i] = make_float4(0.f, 0.f, 0.f, 0.f);

    // This block owns channels [sub*RPB, sub*RPB+RPB) of batch b, all HW.
    const size_t row_base = ((size_t)b * NT * NC + (size_t)sub * RPB) * HW_;

    for (int t = 0; t < NT; t++) {
        const float4* xp = (const float4*)(x   + row_base + (size_t)t * NC * HW_);
        float4*       op = (float4*)      (out + row_base + (size_t)t * NC * HW_);

        // ---- 1) mem = mem*tau + x  (separate mul+add: matches JAX rounding),
        //         per-row partial sums. Bit-identical to R1. ----
        float part[RPB];
        #pragma unroll
        for (int i = 0; i < RPB; i++) {
            float4 xv = __ldcs(xp + i * THREADS + tid);
            float4 m = mem[i];
            m.x = __fadd_rn(__fmul_rn(m.x, tau), xv.x);
            m.y = __fadd_rn(__fmul_rn(m.y, tau), xv.y);
            m.z = __fadd_rn(__fmul_rn(m.z, tau), xv.z);
            m.w = __fadd_rn(__fmul_rn(m.w, tau), xv.w);
            mem[i] = m;
            part[i] = (m.x + m.y) + (m.z + m.w);
        }

        const bool need_tau = (t < NT - 1);   // last step: no MLP/barrier

        if (need_tau) {
            // Warp-reduce each row's partial (identical order to R1).
            #pragma unroll
            for (int i = 0; i < RPB; i++) {
                float v = part[i];
                v += __shfl_xor_sync(0xffffffffu, v, 16);
                v += __shfl_xor_sync(0xffffffffu, v, 8);
                v += __shfl_xor_sync(0xffffffffu, v, 4);
                v += __shfl_xor_sync(0xffffffffu, v, 2);
                v += __shfl_xor_sync(0xffffffffu, v, 1);
                if (lane == 0) s_warp[warp][i] = v;
            }
            __syncthreads();
            // Publish this block's 8 channel sums; release-count per storer.
            if (tid < RPB) {
                float s = 0.f;
                #pragma unroll
                for (int w = 0; w < 8; w++) s += s_warp[w][tid];
                __stcg(&g_sums[b * NC + sub * RPB + tid], s);
                red_release_add(&g_count[b], 1u);
            }
            // Leader: as soon as all 128 publishes arrive, reset the counter
            // and release the generation. NOTHING ELSE on the serial chain.
            if (leader && tid == 0) {
                while (ld_acquire(&g_count[b]) != (unsigned)PUBS) { }
                *(volatile unsigned*)&g_count[b] = 0;   // ordered by release below
                red_release_add(&g_gen[b], 1u);
            }
        }

        // ---- 2) L2 prefetch of x[t+1]: ONE instruction per thread.
        //         Lane l covers line (slice l>>2, line l&3) of this warp's
        //         region: 8 warps x 32 lanes = 256 distinct 128B lines =
        //         the entire 32KB next tile. Overlaps stores + barrier. ----
        if (t + 1 < NT) {
            const char* pb = (const char*)(x + row_base + (size_t)(t + 1) * NC * HW_);
            const char* pa = pb + ((size_t)(lane >> 2) * 4096u)
                                + ((size_t)warp * 512u)
                                + ((size_t)(lane & 3) * 128u);
            asm volatile("prefetch.global.L2 [%0];" :: "l"(pa));
        }

        // ---- 3) spike + output + soft reset (overlaps barrier latency) ----
        #pragma unroll
        for (int i = 0; i < RPB; i++) {
            float4 m = mem[i];
            float4 sp;
            sp.x = (m.x > 1.0f) ? 1.0f : 0.0f;
            sp.y = (m.y > 1.0f) ? 1.0f : 0.0f;
            sp.z = (m.z > 1.0f) ? 1.0f : 0.0f;
            sp.w = (m.w > 1.0f) ? 1.0f : 0.0f;
            __stcs(op + i * THREADS + tid, sp);
            m.x = (m.x > 1.0f) ? 0.0f : m.x;
            m.y = (m.y > 1.0f) ? 0.0f : m.y;
            m.z = (m.z > 1.0f) ? 0.0f : m.z;
            m.w = (m.w > 1.0f) ? 0.0f : m.w;
            mem[i] = m;
        }

        if (!need_tau) break;

        // ---- 4) wait for the generation release (all sums visible) ----
        if (tid == 0) {
            unsigned tgt = base_gen + (unsigned)(t + 1);
            while ((int)(ld_acquire(&g_gen[b]) - tgt) < 0) { }
        }
        __syncthreads();

        // ---- 5) redundant per-block MLP, conflict-free smem access.
        //         Values + fmaf order bit-identical to R1's leader MLP. ----
        if (tid < NC)
            s_mean[tid] = __ldcg(&g_sums[b * NC + tid]) * (1.0f / 1024.0f);
        __syncthreads();
        if (tid < CR) {
            float acc = b1[tid];
            #pragma unroll
            for (int c = 0; c < NC; c++)
                acc = fmaf(s_w1t[c * CR + tid], s_mean[c], acc);   // bank = tid
            float e = fmaxf(acc, 0.0f);        // relu
            float p = e * w2[tid];
            p += __shfl_xor_sync(0xffffffffu, p, 16);
            p += __shfl_xor_sync(0xffffffffu, p, 8);
            p += __shfl_xor_sync(0xffffffffu, p, 4);
            p += __shfl_xor_sync(0xffffffffu, p, 2);
            p += __shfl_xor_sync(0xffffffffu, p, 1);
            if (tid == 0) {
                float z = p + b2[0];
                s_tau = 1.0f / (1.0f + expf(-z));   // sigmoid
            }
        }
        __syncthreads();
        tau = s_tau;
    }
}

extern "C" void kernel_launch(void* const* d_in, const int* in_sizes, int n_in,
                              void* d_out, int out_size)
{
    const float* x  = (const float*)d_in[0];
    const float* w1 = (const float*)d_in[1];
    const float* b1 = (const float*)d_in[2];
    const float* w2 = (const float*)d_in[3];
    const float* b2 = (const float*)d_in[4];
    float* out = (float*)d_out;

    lif_kernel<<<NBLOCKS, THREADS>>>(x, w1, b1, w2, b2, out);
}

// round 9
// speedup vs baseline: 1.3989x; 1.3989x over previous
#include <cuda_runtime.h>

// DynamicLIF persistent kernel for GB300 (sm_103a), round 9.
// Base = R7 (72.7us). Two changes:
//  (1) 32 DEDICATED COORDINATOR BLOCKS (grid 544 = 512 streaming + 32): one
//      per batch, tight-polls g_count[b] and releases g_gen[b]. Streaming
//      blocks never poll -> no leader-warp0 straggling (in R7 the leader
//      blocked mid-step and paced the whole batch serially). Residency:
//      544 <= 592 (4 CTA/SM) -> co-residency proof intact.
//  (2) g_count/g_gen padded to 256B stride: previously all 4096 red.gpu ops
//      per step hit ONE 128B L2 line (serialized ~0.854cyc/op ~ 1.8us/step);
//      now 32 independent LTS slices.
// Race-freedom (same as R7): every block reads base_gen before its first
// publish; no release can precede all 128 publishes. Coordinator resets the
// counter only after the final release (no publisher remains) -> replay-safe.
// Prefetch of ANY kind is dead on this workload (R3/R8 evidence). Tau path
// bit-identical to R7 (rel_err 0.0).

#define NB 32          // batch
#define NT 8           // time steps
#define NC 128         // channels
#define HW_ 1024       // H*W
#define CR 32          // C / red
#define THREADS 256
#define RPB 8          // channel rows per block
#define BPB 16         // streaming blocks per batch
#define NSTREAM (NB * BPB)       // 512
#define NBLOCKS (NSTREAM + NB)   // 544 (32 coordinators)
#define PUBS (BPB * RPB)         // 128 count-releases per batch per step
#define CPAD 64        // 256B stride for per-batch counters

__device__ float    g_sums[NB * NC];
__device__ unsigned g_count[NB * CPAD];  // zero at launch; coordinator resets at end
__device__ unsigned g_gen[NB * CPAD];    // monotonic across replays

__device__ __forceinline__ unsigned ld_acquire(const unsigned* p) {
    unsigned v;
    asm volatile("ld.acquire.gpu.global.u32 %0, [%1];" : "=r"(v) : "l"(p));
    return v;
}
__device__ __forceinline__ void red_release_add(unsigned* p, unsigned v) {
    asm volatile("red.release.gpu.global.add.u32 [%0], %1;" :: "l"(p), "r"(v));
}

__global__ void __launch_bounds__(THREADS, 4)
lif_kernel(const float* __restrict__ x,
           const float* __restrict__ w1,
           const float* __restrict__ b1,
           const float* __restrict__ w2,
           const float* __restrict__ b2,
           float* __restrict__ out)
{
    __shared__ float s_w1t[NC * CR];   // 16 KB, TRANSPOSED: [c][row]
    __shared__ float s_warp[8][RPB];
    __shared__ float s_mean[NC];
    __shared__ float s_tau;

    const int tid = threadIdx.x;
    const int blk = blockIdx.x;

    // ---------------- coordinator blocks (one per batch) ----------------
    if (blk >= NSTREAM) {
        if (tid == 0) {
            const int bb = blk - NSTREAM;
            unsigned* cnt = &g_count[bb * CPAD];
            unsigned* gen = &g_gen[bb * CPAD];
            #pragma unroll 1
            for (int t = 0; t < NT - 1; t++) {
                unsigned tgt = (unsigned)PUBS * (unsigned)(t + 1);
                while (ld_acquire(cnt) < tgt) { }
                red_release_add(gen, 1u);     // acquire->release chain keeps
            }                                  // publishers' sums visible
            // All 896 publishes of this launch observed -> no publisher
            // remains. Reset for the next graph replay (ordered by kernel
            // completion boundary).
            *(volatile unsigned*)cnt = 0;
        }
        return;
    }

    // ---------------- streaming blocks ----------------
    const int b   = blk >> 4;          // batch
    const int sub = blk & 15;          // sub-block within batch
    const int lane = tid & 31;
    const int warp = tid >> 5;
    unsigned* const cnt = &g_count[b * CPAD];
    unsigned* const gen = &g_gen[b * CPAD];

    // Cache w1 transposed: s_w1t[c*CR + r] = w1[r*NC + c] (conflict-free MLP).
    #pragma unroll
    for (int i = 0; i < (CR * NC) / THREADS; i++) {
        int idx = i * THREADS + tid;
        int r = idx >> 7;
        int c = idx & 127;
        s_w1t[c * CR + r] = w1[idx];
    }
    __syncthreads();

    // base_gen read precedes this block's first publish (program order), and
    // no release can happen until all 16 blocks publish -> race-free across
    // startup skew AND graph replays.
    unsigned base_gen = 0;
    if (tid == 0) base_gen = *(volatile unsigned*)gen;

    float tau = 0.5f;                  // TAU0
    float4 mem[RPB];
    #pragma unroll
    for (int i = 0; i < RPB; i++) mem[i] = make_float4(0.f, 0.f, 0.f, 0.f);

    // This block owns channels [sub*RPB, sub*RPB+RPB) of batch b, all HW.
    const size_t row_base = ((size_t)b * NT * NC + (size_t)sub * RPB) * HW_;

    for (int t = 0; t < NT; t++) {
        const float4* xp = (const float4*)(x   + row_base + (size_t)t * NC * HW_);
        float4*       op = (float4*)      (out + row_base + (size_t)t * NC * HW_);

        // ---- 1) mem = mem*tau + x  (separate mul+add: matches JAX rounding),
        //         per-row partial sums. Bit-identical to R1/R7. ----
        float part[RPB];
        #pragma unroll
        for (int i = 0; i < RPB; i++) {
            float4 xv = __ldcs(xp + i * THREADS + tid);
            float4 m = mem[i];
            m.x = __fadd_rn(__fmul_rn(m.x, tau), xv.x);
            m.y = __fadd_rn(__fmul_rn(m.y, tau), xv.y);
            m.z = __fadd_rn(__fmul_rn(m.z, tau), xv.z);
            m.w = __fadd_rn(__fmul_rn(m.w, tau), xv.w);
            mem[i] = m;
            part[i] = (m.x + m.y) + (m.z + m.w);
        }

        const bool need_tau = (t < NT - 1);   // last step: no MLP/barrier

        if (need_tau) {
            // Warp-reduce each row's partial (identical order to R1).
            #pragma unroll
            for (int i = 0; i < RPB; i++) {
                float v = part[i];
                v += __shfl_xor_sync(0xffffffffu, v, 16);
                v += __shfl_xor_sync(0xffffffffu, v, 8);
                v += __shfl_xor_sync(0xffffffffu, v, 4);
                v += __shfl_xor_sync(0xffffffffu, v, 2);
                v += __shfl_xor_sync(0xffffffffu, v, 1);
                if (lane == 0) s_warp[warp][i] = v;
            }
            __syncthreads();
            // Publish this block's 8 channel sums; release-count per storer.
            // No polling here -- the coordinator handles release.
            if (tid < RPB) {
                float s = 0.f;
                #pragma unroll
                for (int w = 0; w < 8; w++) s += s_warp[w][tid];
                __stcg(&g_sums[b * NC + sub * RPB + tid], s);
                red_release_add(cnt, 1u);
            }
        }

        // ---- 2) spike + output + soft reset (overlaps barrier latency) ----
        #pragma unroll
        for (int i = 0; i < RPB; i++) {
            float4 m = mem[i];
            float4 sp;
            sp.x = (m.x > 1.0f) ? 1.0f : 0.0f;
            sp.y = (m.y > 1.0f) ? 1.0f : 0.0f;
            sp.z = (m.z > 1.0f) ? 1.0f : 0.0f;
            sp.w = (m.w > 1.0f) ? 1.0f : 0.0f;
            __stcs(op + i * THREADS + tid, sp);
            m.x = (m.x > 1.0f) ? 0.0f : m.x;
            m.y = (m.y > 1.0f) ? 0.0f : m.y;
            m.z = (m.z > 1.0f) ? 0.0f : m.z;
            m.w = (m.w > 1.0f) ? 0.0f : m.w;
            mem[i] = m;
        }

        if (!need_tau) break;

        // ---- 3) wait for the coordinator's generation release ----
        if (tid == 0) {
            unsigned tgt = base_gen + (unsigned)(t + 1);
            while ((int)(ld_acquire(gen) - tgt) < 0) { }
        }
        __syncthreads();

        // ---- 4) redundant per-block MLP, conflict-free smem access.
        //         Values + fmaf order bit-identical to R1's leader MLP. ----
        if (tid < NC)
            s_mean[tid] = __ldcg(&g_sums[b * NC + tid]) * (1.0f / 1024.0f);
        __syncthreads();
        if (tid < CR) {
            float acc = b1[tid];
            #pragma unroll
            for (int c = 0; c < NC; c++)
                acc = fmaf(s_w1t[c * CR + tid], s_mean[c], acc);   // bank = tid
            float e = fmaxf(acc, 0.0f);        // relu
            float p = e * w2[tid];
            p += __shfl_xor_sync(0xffffffffu, p, 16);
            p += __shfl_xor_sync(0xffffffffu, p, 8);
            p += __shfl_xor_sync(0xffffffffu, p, 4);
            p += __shfl_xor_sync(0xffffffffu, p, 2);
            p += __shfl_xor_sync(0xffffffffu, p, 1);
            if (tid == 0) {
                float z = p + b2[0];
                s_tau = 1.0f / (1.0f + expf(-z));   // sigmoid
            }
        }
        __syncthreads();
        tau = s_tau;
    }
}

extern "C" void kernel_launch(void* const* d_in, const int* in_sizes, int n_in,
                              void* d_out, int out_size)
{
    const float* x  = (const float*)d_in[0];
    const float* w1 = (const float*)d_in[1];
    const float* b1 = (const float*)d_in[2];
    const float* w2 = (const float*)d_in[3];
    const float* b2 = (const float*)d_in[4];
    float* out = (float*)d_out;

    lif_kernel<<<NBLOCKS, THREADS>>>(x, w1, b1, w2, b2, out);
}

// round 10
// speedup vs baseline: 1.5202x; 1.0867x over previous
#include <cuda_runtime.h>

// DynamicLIF persistent kernel for GB300 (sm_103a), round 10.
// Base = R9 (70.6us). Changes:
//  (1) The tau-MLP moves ENTIRELY into the 32 dedicated coordinator blocks,
//      where it runs overlapped with the streaming blocks' 2.6us store
//      burst. Streaming blocks do ZERO post-store work beyond one poll.
//  (2) tau is PACKED into the release word: g_sync[b] = (gen<<32)|tau_bits,
//      st.release.gpu.u64. Spinners get generation + tau in ONE L2 load.
//      Overshoot impossible: gen cannot reach t+2 until all blocks publish
//      step t+2, which requires them to pass gen t+1 first.
//  (3) Streaming blocks drop the w1 smem cache + MLP (leaner prologue/tail).
// MLP values/order identical to R7/R9 (rel_err 0.0). Race-freedom: base-gen
// read precedes each block's first publish; no release precedes all 128
// publishes; counter reset only after the final release of the launch.

#define NB 32          // batch
#define NT 8           // time steps
#define NC 128         // channels
#define HW_ 1024       // H*W
#define CR 32          // C / red
#define THREADS 256
#define RPB 8          // channel rows per block
#define BPB 16         // streaming blocks per batch
#define NSTREAM (NB * BPB)       // 512
#define NBLOCKS (NSTREAM + NB)   // 544 (32 coordinators)
#define PUBS (BPB * RPB)         // 128 count-releases per batch per step
#define CPAD 64        // 256B stride for g_count (unsigned)
#define SPAD 32        // 256B stride for g_sync (u64)

__device__ float              g_sums[NB * NC];
__device__ unsigned           g_count[NB * CPAD]; // zero at launch; coord resets at end
__device__ unsigned long long g_sync[NB * SPAD];  // (gen<<32)|tau_bits, monotonic gen

__device__ __forceinline__ unsigned ld_acquire_u32(const unsigned* p) {
    unsigned v;
    asm volatile("ld.acquire.gpu.global.u32 %0, [%1];" : "=r"(v) : "l"(p));
    return v;
}
__device__ __forceinline__ unsigned long long ld_acquire_u64(const unsigned long long* p) {
    unsigned long long v;
    asm volatile("ld.acquire.gpu.global.u64 %0, [%1];" : "=l"(v) : "l"(p));
    return v;
}
__device__ __forceinline__ void st_release_u64(unsigned long long* p, unsigned long long v) {
    asm volatile("st.release.gpu.global.u64 [%0], %1;" :: "l"(p), "l"(v));
}
__device__ __forceinline__ void red_release_add(unsigned* p, unsigned v) {
    asm volatile("red.release.gpu.global.add.u32 [%0], %1;" :: "l"(p), "r"(v));
}

__global__ void __launch_bounds__(THREADS, 4)
lif_kernel(const float* __restrict__ x,
           const float* __restrict__ w1,
           const float* __restrict__ b1,
           const float* __restrict__ w2,
           const float* __restrict__ b2,
           float* __restrict__ out)
{
    const int tid = threadIdx.x;
    const int blk = blockIdx.x;
    const int lane = tid & 31;
    const int warp = tid >> 5;

    // ---------------- coordinator blocks (one per batch) ----------------
    if (blk >= NSTREAM) {
        __shared__ float s_w1t[NC * CR];   // 16 KB, TRANSPOSED: [c][row]
        __shared__ float s_mean[NC];

        const int bb = blk - NSTREAM;
        unsigned*           cnt = &g_count[bb * CPAD];
        unsigned long long* syn = &g_sync[bb * SPAD];

        // Cache w1 transposed (conflict-free MLP reads).
        #pragma unroll
        for (int i = 0; i < (CR * NC) / THREADS; i++) {
            int idx = i * THREADS + tid;
            s_w1t[(idx & 127) * CR + (idx >> 7)] = w1[idx];
        }

        unsigned base_gen = 0;
        if (tid == 0) base_gen = (unsigned)(*(volatile unsigned long long*)syn >> 32);
        __syncthreads();

        #pragma unroll 1
        for (int t = 0; t < NT - 1; t++) {
            // Wait for all 128 publishes of step t.
            if (tid == 0) {
                unsigned tgt = (unsigned)PUBS * (unsigned)(t + 1);
                while (ld_acquire_u32(cnt) < tgt) { }
            }
            __syncthreads();   // acquire by t0 + barrier -> sums visible to block

            // MLP: values + order byte-identical to R7/R9.
            if (tid < NC)
                s_mean[tid] = __ldcg(&g_sums[bb * NC + tid]) * (1.0f / 1024.0f);
            __syncthreads();
            if (tid < CR) {
                float acc = b1[tid];
                #pragma unroll
                for (int c = 0; c < NC; c++)
                    acc = fmaf(s_w1t[c * CR + tid], s_mean[c], acc);
                float e = fmaxf(acc, 0.0f);        // relu
                float p = e * w2[tid];
                p += __shfl_xor_sync(0xffffffffu, p, 16);
                p += __shfl_xor_sync(0xffffffffu, p, 8);
                p += __shfl_xor_sync(0xffffffffu, p, 4);
                p += __shfl_xor_sync(0xffffffffu, p, 2);
                p += __shfl_xor_sync(0xffffffffu, p, 1);
                if (tid == 0) {
                    float z = p + b2[0];
                    float tn = 1.0f / (1.0f + expf(-z));   // sigmoid
                    unsigned long long v =
                        ((unsigned long long)(base_gen + (unsigned)(t + 1)) << 32)
                        | (unsigned long long)__float_as_uint(tn);
                    st_release_u64(syn, v);   // gen + tau in one word
                }
            }
            __syncthreads();
        }
        // All 896 publishes observed -> no publisher remains. Reset for the
        // next graph replay (ordered by the kernel completion boundary).
        if (tid == 0) *(volatile unsigned*)cnt = 0;
        return;
    }

    // ---------------- streaming blocks ----------------
    __shared__ float s_warp[8][RPB];
    __shared__ float s_tau;

    const int b   = blk >> 4;          // batch
    const int sub = blk & 15;          // sub-block within batch
    unsigned*           const cnt = &g_count[b * CPAD];
    unsigned long long* const syn = &g_sync[b * SPAD];

    // base_gen read precedes this block's first publish (program order), and
    // no release can happen until all 16 blocks publish -> race-free across
    // startup skew AND graph replays.
    unsigned base_gen = 0;
    if (tid == 0) base_gen = (unsigned)(*(volatile unsigned long long*)syn >> 32);

    float tau = 0.5f;                  // TAU0
    float4 mem[RPB];
    #pragma unroll
    for (int i = 0; i < RPB; i++) mem[i] = make_float4(0.f, 0.f, 0.f, 0.f);

    // This block owns channels [sub*RPB, sub*RPB+RPB) of batch b, all HW.
    const size_t row_base = ((size_t)b * NT * NC + (size_t)sub * RPB) * HW_;

    for (int t = 0; t < NT; t++) {
        const float4* xp = (const float4*)(x   + row_base + (size_t)t * NC * HW_);
        float4*       op = (float4*)      (out + row_base + (size_t)t * NC * HW_);

        // ---- 1) mem = mem*tau + x  (separate mul+add: matches JAX rounding),
        //         per-row partial sums. Bit-identical to R1/R7/R9. ----
        float part[RPB];
        #pragma unroll
        for (int i = 0; i < RPB; i++) {
            float4 xv = __ldcs(xp + i * THREADS + tid);
            float4 m = mem[i];
            m.x = __fadd_rn(__fmul_rn(m.x, tau), xv.x);
            m.y = __fadd_rn(__fmul_rn(m.y, tau), xv.y);
            m.z = __fadd_rn(__fmul_rn(m.z, tau), xv.z);
            m.w = __fadd_rn(__fmul_rn(m.w, tau), xv.w);
            mem[i] = m;
            part[i] = (m.x + m.y) + (m.z + m.w);
        }

        const bool need_tau = (t < NT - 1);   // last step: no publish/wait

        if (need_tau) {
            // Warp-reduce each row's partial (identical order to R1).
            #pragma unroll
            for (int i = 0; i < RPB; i++) {
                float v = part[i];
                v += __shfl_xor_sync(0xffffffffu, v, 16);
                v += __shfl_xor_sync(0xffffffffu, v, 8);
                v += __shfl_xor_sync(0xffffffffu, v, 4);
                v += __shfl_xor_sync(0xffffffffu, v, 2);
                v += __shfl_xor_sync(0xffffffffu, v, 1);
                if (lane == 0) s_warp[warp][i] = v;
            }
            __syncthreads();
            // Publish this block's 8 channel sums; release-count per storer.
            if (tid < RPB) {
                float s = 0.f;
                #pragma unroll
                for (int w = 0; w < 8; w++) s += s_warp[w][tid];
                __stcg(&g_sums[b * NC + sub * RPB + tid], s);
                red_release_add(cnt, 1u);
            }
        }

        // ---- 2) spike + output + soft reset (overlaps coordinator MLP) ----
        #pragma unroll
        for (int i = 0; i < RPB; i++) {
            float4 m = mem[i];
            float4 sp;
            sp.x = (m.x > 1.0f) ? 1.0f : 0.0f;
            sp.y = (m.y > 1.0f) ? 1.0f : 0.0f;
            sp.z = (m.z > 1.0f) ? 1.0f : 0.0f;
            sp.w = (m.w > 1.0f) ? 1.0f : 0.0f;
            __stcs(op + i * THREADS + tid, sp);
            m.x = (m.x > 1.0f) ? 0.0f : m.x;
            m.y = (m.y > 1.0f) ? 0.0f : m.y;
            m.z = (m.z > 1.0f) ? 0.0f : m.z;
            m.w = (m.w > 1.0f) ? 0.0f : m.w;
            mem[i] = m;
        }

        if (!need_tau) break;

        // ---- 3) single poll: generation + tau arrive together ----
        if (tid == 0) {
            unsigned tgt = base_gen + (unsigned)(t + 1);
            unsigned long long v;
            do {
                v = ld_acquire_u64(syn);
            } while ((int)((unsigned)(v >> 32) - tgt) < 0);
            s_tau = __uint_as_float((unsigned)v);
        }
        __syncthreads();
        tau = s_tau;
    }
}

extern "C" void kernel_launch(void* const* d_in, const int* in_sizes, int n_in,
                              void* d_out, int out_size)
{
    const float* x  = (const float*)d_in[0];
    const float* w1 = (const float*)d_in[1];
    const float* b1 = (const float*)d_in[2];
    const float* w2 = (const float*)d_in[3];
    const float* b2 = (const float*)d_in[4];
    float* out = (float*)d_out;

    lif_kernel<<<NBLOCKS, THREADS>>>(x, w1, b1, w2, b2, out);
}